// round 13
// baseline (speedup 1.0000x reference)
#include <cuda_runtime.h>
#include <math_constants.h>
#include <stdint.h>

#define B  32
#define N  8192
#define K  128
#define PS 32

#define CAPC 128        // accept window upper bound
#define CAPF 512        // stuck-bracket collect cap
#define NSM  148        // grid = 148 CTAs (1/SM, all resident wave 1)
#define KNNC (NSM - B)  // 116 KNN worker CTAs
#define UNITS (B * K / 2)  // 2048 row-pairs
#define THRK 1024

typedef unsigned long long u64;
typedef unsigned short u16;

// Scratch (allocation-free rule: __device__ globals)
__device__ float g_centers[B * K * 3];
__device__ int   g_prog[B];

// ---------------------------------------------------------------------------
// f32x2 packed helpers (one fma-pipe instr = 2 IEEE .rn ops, bit-identical)
// ---------------------------------------------------------------------------
__device__ __forceinline__ u64 pack2(float lo, float hi) {
    u64 r; asm("mov.b64 %0, {%1, %2};" : "=l"(r) : "f"(lo), "f"(hi)); return r;
}
__device__ __forceinline__ float2 unpack2(u64 v) {
    float2 f; asm("mov.b64 {%0, %1}, %2;" : "=f"(f.x), "=f"(f.y) : "l"(v)); return f;
}
__device__ __forceinline__ u64 add2(u64 a, u64 b) {
    u64 d; asm("add.rn.f32x2 %0, %1, %2;" : "=l"(d) : "l"(a), "l"(b)); return d;
}
__device__ __forceinline__ u64 mul2(u64 a, u64 b) {
    u64 d; asm("mul.rn.f32x2 %0, %1, %2;" : "=l"(d) : "l"(a), "l"(b)); return d;
}
__device__ __forceinline__ u64 fma2(u64 a, u64 b, u64 c) {
    u64 d; asm("fma.rn.f32x2 %0, %1, %2, %3;" : "=l"(d) : "l"(a), "l"(b), "l"(c)); return d;
}

// release publish / acquire poll
__device__ __forceinline__ void red_release_add(int* p) {
    asm volatile("red.release.gpu.global.add.s32 [%0], 1;" :: "l"(p) : "memory");
}
__device__ __forceinline__ int ld_acquire(const int* p) {
    int v;
    asm volatile("ld.acquire.gpu.global.s32 %0, [%1];" : "=r"(v) : "l"(p) : "memory");
    return v;
}

// ---------------------------------------------------------------------------
// Exact key (explicit intrinsics, bit-identical everywhere it is called)
// ---------------------------------------------------------------------------
__device__ __forceinline__ unsigned f2key(float f) {
    unsigned bits = __float_as_uint(f);
    return (bits & 0x80000000u) ? ~bits : (bits | 0x80000000u);
}
__device__ __forceinline__ unsigned d2key(float px, float py, float pz,
                                          float cx, float cy, float cz, float cc) {
    float pp  = __fmaf_rn(pz, pz, __fmaf_rn(py, py, __fmul_rn(px, px)));
    float dot = __fmaf_rn(cz, pz, __fmaf_rn(cy, py, __fmul_rn(cx, px)));
    float d2  = __fmaf_rn(-2.0f, dot, __fadd_rn(cc, pp));
    return f2key(d2);
}

// ---------------------------------------------------------------------------
// Zero the progress flags (graph-replay safe init, stream-ordered)
// ---------------------------------------------------------------------------
extern "C" __global__ void zero_prog() {
    if (threadIdx.x < B) g_prog[threadIdx.x] = 0;
}

// ---------------------------------------------------------------------------
// FUSED kernel: CTAs [0,32) = FPS (one per batch), CTAs [32,148) = KNN
// workers consuming centers as FPS publishes them (release/acquire on
// g_prog[b]). Grid 148, 1024 thr, 96KB smem -> 1 CTA/SM, all resident.
// ---------------------------------------------------------------------------
extern "C" __global__ void __launch_bounds__(1024, 1)
fused_kernel(const float* __restrict__ points, void* __restrict__ d_out,
             int is_f32) {
    extern __shared__ char smraw[];

    const int t = threadIdx.x;
    const int lane = t & 31, w = t >> 5;

    if (blockIdx.x < B) {
        // ===================== FPS role (R12-proven) =====================
        float* pts = (float*)smraw;          // [N*3] = 96KB
        __shared__ unsigned s_maxb[K];
        __shared__ int      s_idx[K];

        const int b = blockIdx.x;
        const float* gp = points + (size_t)b * N * 3;

        for (int i = t; i < N * 3; i += 1024) pts[i] = gp[i];
        if (t < K) { s_maxb[t] = 0u; s_idx[t] = 0x7fffffff; }
        __syncthreads();

        u64 px2[4], py2[4], pz2[4];
        float md[8];
#pragma unroll
        for (int j = 0; j < 4; j++) {
            int nlo = t + (2 * j) * 1024;
            int nhi = t + (2 * j + 1) * 1024;
            px2[j] = pack2(pts[3 * nlo + 0], pts[3 * nhi + 0]);
            py2[j] = pack2(pts[3 * nlo + 1], pts[3 * nhi + 1]);
            pz2[j] = pack2(pts[3 * nlo + 2], pts[3 * nhi + 2]);
            md[2 * j] = CUDART_INF_F; md[2 * j + 1] = CUDART_INF_F;
        }

        int cur = 0;
        for (int k = 0; k < K; k++) {
            float cx = pts[3 * cur + 0];
            float cy = pts[3 * cur + 1];
            float cz = pts[3 * cur + 2];
            if (t == 0) {
                g_centers[(b * K + k) * 3 + 0] = cx;
                g_centers[(b * K + k) * 3 + 1] = cy;
                g_centers[(b * K + k) * 3 + 2] = cz;
                red_release_add(&g_prog[b]);   // publish center k
            }
            u64 nc2x = pack2(-cx, -cx);
            u64 nc2y = pack2(-cy, -cy);
            u64 nc2z = pack2(-cz, -cz);
#pragma unroll
            for (int j = 0; j < 4; j++) {
                u64 dx = add2(px2[j], nc2x);
                u64 dy = add2(py2[j], nc2y);
                u64 dz = add2(pz2[j], nc2z);
                u64 d  = mul2(dx, dx);
                d = fma2(dy, dy, d);
                d = fma2(dz, dz, d);
                float2 f = unpack2(d);
                md[2 * j]     = fminf(md[2 * j],     f.x);
                md[2 * j + 1] = fminf(md[2 * j + 1], f.y);
            }
            float tv = fmaxf(fmaxf(fmaxf(md[0], md[1]), fmaxf(md[2], md[3])),
                             fmaxf(fmaxf(md[4], md[5]), fmaxf(md[6], md[7])));
            unsigned wv = __reduce_max_sync(0xffffffffu, __float_as_uint(tv));
            if (lane == 0) atomicMax(&s_maxb[k], wv);
            __syncthreads();
            const unsigned mb = s_maxb[k];
            if (wv == mb) {
                int li = 0x7fffffff;
#pragma unroll
                for (int s = 0; s < 8; s++) {
                    if (__float_as_uint(md[s]) == mb) li = min(li, t + s * 1024);
                }
                if (li != 0x7fffffff) atomicMin(&s_idx[k], li);
            }
            __syncthreads();
            cur = s_idx[k];
        }
        return;
    }

    // ======================= KNN worker role ===========================
    u16* s_pre = (u16*)smraw;                      // RPC2*N*2 = 32KB
    u64* s_cp  = (u64*)(smraw + 2 * N * 2);        // CAPF*8   =  4KB

    __shared__ unsigned s_wmin[THRK / 32];
    __shared__ int      s_cnt;
    __shared__ u64      s_minw[THRK / 32];
    __shared__ u64      s_last;

    const int c = blockIdx.x - B;
    const int NW = THRK / 32;
    const unsigned lmask_lt = (1u << lane) - 1u;

    for (int u = c; u < UNITS; u += KNNC) {
        const int k2 = u >> 5;          // k-pair index (k-major order)
        const int b  = u & 31;
        const int row0 = b * K + 2 * k2;
        const float* gp = points + (size_t)b * N * 3;

        // wait until both centers published
        if (t == 0) {
            const int target = 2 * k2 + 2;
            while (ld_acquire(&g_prog[b]) < target) { }
        }
        __syncthreads();

        float cx[2], cy[2], cz[2], cc[2];
#pragma unroll
        for (int r = 0; r < 2; r++) {
            const float* cp = &g_centers[(row0 + r) * 3];
            cx[r] = __ldcg(cp + 0); cy[r] = __ldcg(cp + 1); cz[r] = __ldcg(cp + 2);
            cc[r] = __fmaf_rn(cz[r], cz[r],
                    __fmaf_rn(cy[r], cy[r], __fmul_rn(cx[r], cx[r])));
        }

        // Pass 1: one point read serves both rows
        unsigned tmin0 = 0xffffu, tmin1 = 0xffffu;
#pragma unroll 4
        for (int j = 0; j < N / THRK; j++) {
            int n = t + j * THRK;
            float px = gp[3 * n + 0], py = gp[3 * n + 1], pz = gp[3 * n + 2];
            unsigned p0 = d2key(px, py, pz, cx[0], cy[0], cz[0], cc[0]) >> 16;
            unsigned p1 = d2key(px, py, pz, cx[1], cy[1], cz[1], cc[1]) >> 16;
            s_pre[n]     = (u16)p0;
            s_pre[N + n] = (u16)p1;
            tmin0 = min(tmin0, p0);
            tmin1 = min(tmin1, p1);
        }

        for (int r = 0; r < 2; r++) {
            const u16* pre_row = &s_pre[r * N];
            const int  row = row0 + r;
            unsigned tmin = (r == 0) ? tmin0 : tmin1;

            tmin = __reduce_min_sync(0xffffffffu, tmin);
            if (lane == 0) s_wmin[w] = tmin;
            __syncthreads();

            unsigned probe = 0u;
#pragma unroll
            for (int i = 0; i < NW; i++) probe = max(probe, s_wmin[i]);

            unsigned klo = 0u, khi = 0xffffu;
            int chi = N;
            unsigned T = 0u;
            bool have = false;
            for (int iter = 0; iter < 18; iter++) {
                if (t == 0) s_cnt = 0;
                __syncthreads();
                int cN = 0;
#pragma unroll
                for (int j = 0; j < N / THRK; j++)
                    cN += (pre_row[t + j * THRK] <= (u16)probe);
                cN = __reduce_add_sync(0xffffffffu, cN);
                if (lane == 0) atomicAdd(&s_cnt, cN);
                __syncthreads();
                int cnt = s_cnt;
                __syncthreads();               // protect next reset
                if (cnt >= PS && cnt <= CAPC) { T = probe; have = true; break; }
                if (cnt < PS) klo = probe; else { khi = probe; chi = cnt; }
                if (khi - klo <= 1u) break;

                unsigned next = klo + ((khi - klo) >> 1);
                if ((iter % 3) != 2 && probe >= 0x8000u && cnt > 0) {
                    float d = __uint_as_float((probe << 16) & 0x7fffffffu);
                    float cand = d * __powf(64.0f / (float)cnt, 0.6666667f);
                    if (cand > 0.0f) {
                        unsigned ck = (__float_as_uint(cand) | 0x80000000u) >> 16;
                        if (ck > klo && ck < khi) next = ck;
                    }
                }
                probe = next;
            }
            if (!have && chi <= CAPF) { T = khi; have = true; }

            if (have) {
                if (t == 0) s_cnt = 0;
                __syncthreads();
#pragma unroll
                for (int j = 0; j < N / THRK; j++) {
                    int n = t + j * THRK;
                    bool p = (pre_row[n] <= (u16)T);
                    unsigned m = __ballot_sync(0xffffffffu, p);
                    if (m) {
                        int leader = __ffs(m) - 1;
                        int base = 0;
                        if (lane == leader) base = atomicAdd(&s_cnt, __popc(m));
                        base = __shfl_sync(0xffffffffu, base, leader);
                        if (p) {
                            int pos = base + __popc(m & lmask_lt);
                            if (pos < CAPF) s_cp[pos] = (u64)(unsigned)n;
                        }
                    }
                }
                __syncthreads();
                const int C = min(s_cnt, CAPF);
                for (int i = t; i < C; i += THRK) {
                    int n = (int)(unsigned)s_cp[i];
                    float px = gp[3 * n + 0], py = gp[3 * n + 1], pz = gp[3 * n + 2];
                    unsigned key = d2key(px, py, pz, cx[r], cy[r], cz[r], cc[r]);
                    s_cp[i] = ((u64)key << 32) | (unsigned)n;
                }
                __syncthreads();
                for (int jj = t; jj < C; jj += THRK) {
                    u64 me = s_cp[jj];
                    int rk = 0;
                    for (int m = 0; m < C; m++) rk += (s_cp[m] < me);
                    if (rk < PS) {
                        int nj = (int)(unsigned)(me & 0xffffffffu);
                        if (is_f32) ((float*)d_out)[row * PS + rk] = (float)nj;
                        else        ((int*)d_out)[row * PS + rk] = nj;
                    }
                }
            } else {
                // exact fallback (measure zero)
                if (t == 0) s_last = 0ull;
                __syncthreads();
                for (int sel = 0; sel < PS; sel++) {
                    u64 last = s_last;
                    u64 best = 0xffffffffffffffffull;
                    for (int j = 0; j < N / THRK; j++) {
                        int n = t + j * THRK;
                        float px = gp[3 * n + 0], py = gp[3 * n + 1], pz = gp[3 * n + 2];
                        unsigned key = d2key(px, py, pz, cx[r], cy[r], cz[r], cc[r]);
                        u64 v = ((u64)key << 32) | (unsigned)n;
                        if (v > last && v < best) best = v;
                    }
#pragma unroll
                    for (int off = 16; off; off >>= 1) {
                        u64 o = __shfl_down_sync(0xffffffffu, best, off);
                        best = o < best ? o : best;
                    }
                    if (lane == 0) s_minw[w] = best;
                    __syncthreads();
                    if (t == 0) {
                        u64 m = s_minw[0];
                        for (int i = 1; i < NW; i++) m = s_minw[i] < m ? s_minw[i] : m;
                        int nj = (int)(unsigned)(m & 0xffffffffu);
                        if (is_f32) ((float*)d_out)[row * PS + sel] = (float)nj;
                        else        ((int*)d_out)[row * PS + sel] = nj;
                        s_last = m;
                    }
                    __syncthreads();
                }
            }
            __syncthreads();
        }
    }
}

// ---------------------------------------------------------------------------
// Centers epilogue (f32 layout only)
// ---------------------------------------------------------------------------
extern "C" __global__ void epilogue_centers(float* __restrict__ out, int out_size) {
    int i = blockIdx.x * 256 + threadIdx.x;
    int dst = B * K * PS + i;
    if (i < B * K * 3 && dst < out_size) out[dst] = g_centers[i];
}

// ---------------------------------------------------------------------------
extern "C" void kernel_launch(void* const* d_in, const int* in_sizes, int n_in,
                              void* d_out, int out_size) {
    (void)in_sizes; (void)n_in;
    const float* points = (const float*)d_in[0];

    const int fused_smem = N * 3 * (int)sizeof(float);   // 96KB
    cudaFuncSetAttribute(fused_kernel,
                         cudaFuncAttributeMaxDynamicSharedMemorySize, fused_smem);

    const int is_f32 = (out_size != B * K * PS);

    zero_prog<<<1, 32>>>();
    fused_kernel<<<NSM, THRK, fused_smem>>>(points, d_out, is_f32);

    if (is_f32) {
        int nc = B * K * 3;
        epilogue_centers<<<(nc + 255) / 256, 256>>>((float*)d_out, out_size);
    }
}

// round 14
// speedup vs baseline: 1.3130x; 1.3130x over previous
#include <cuda_runtime.h>
#include <math_constants.h>
#include <stdint.h>

#define B  32
#define N  8192
#define K  128
#define PS 32

#define CAPC 128        // accept window upper bound (sort stays tiny)
#define CAPF 512        // stuck-bracket collect cap
#define RPC  2          // rows per CTA (shared point reads)
#define THR  512        // KNN threads per CTA

typedef unsigned long long u64;
typedef unsigned short u16;

// Scratch (allocation-free rule: __device__ globals)
__device__ float g_centers[B * K * 3];

// ---------------------------------------------------------------------------
// f32x2 packed helpers (one fma-pipe instr = 2 IEEE .rn ops, bit-identical)
// ---------------------------------------------------------------------------
__device__ __forceinline__ u64 pack2(float lo, float hi) {
    u64 r; asm("mov.b64 %0, {%1, %2};" : "=l"(r) : "f"(lo), "f"(hi)); return r;
}
__device__ __forceinline__ float2 unpack2(u64 v) {
    float2 f; asm("mov.b64 {%0, %1}, %2;" : "=f"(f.x), "=f"(f.y) : "l"(v)); return f;
}
__device__ __forceinline__ u64 add2(u64 a, u64 b) {
    u64 d; asm("add.rn.f32x2 %0, %1, %2;" : "=l"(d) : "l"(a), "l"(b)); return d;
}
__device__ __forceinline__ u64 mul2(u64 a, u64 b) {
    u64 d; asm("mul.rn.f32x2 %0, %1, %2;" : "=l"(d) : "l"(a), "l"(b)); return d;
}
__device__ __forceinline__ u64 fma2(u64 a, u64 b, u64 c) {
    u64 d; asm("fma.rn.f32x2 %0, %1, %2, %3;" : "=l"(d) : "l"(a), "l"(b), "l"(c)); return d;
}

// ---------------------------------------------------------------------------
// FPS: one block/batch, 1024 threads, f32x2 math. ONE barrier per iteration,
// NO atomics: per-warp (REDUX max val, REDUX min idx) -> double-buffered smem
// slots -> every warp redundantly reduces the 32 pairs (2 LDS + 2 REDUX) and
// computes cur locally. Exact jnp.argmax first-occurrence semantics.
// ---------------------------------------------------------------------------
extern "C" __global__ void __launch_bounds__(1024, 1)
fps_kernel(const float* __restrict__ points) {
    extern __shared__ float pts[];      // [N*3] = 96KB
    __shared__ unsigned s_v[2][32];
    __shared__ unsigned s_i[2][32];

    const int b = blockIdx.x;
    const int t = threadIdx.x;
    const float* gp = points + (size_t)b * N * 3;

    for (int i = t; i < N * 3; i += 1024) pts[i] = gp[i];
    __syncthreads();

    u64 px2[4], py2[4], pz2[4];
    float md[8];
#pragma unroll
    for (int j = 0; j < 4; j++) {
        int nlo = t + (2 * j) * 1024;
        int nhi = t + (2 * j + 1) * 1024;
        px2[j] = pack2(pts[3 * nlo + 0], pts[3 * nhi + 0]);
        py2[j] = pack2(pts[3 * nlo + 1], pts[3 * nhi + 1]);
        pz2[j] = pack2(pts[3 * nlo + 2], pts[3 * nhi + 2]);
        md[2 * j] = CUDART_INF_F; md[2 * j + 1] = CUDART_INF_F;
    }

    int cur = 0;
    const int lane = t & 31, w = t >> 5;
    for (int k = 0; k < K; k++) {
        float cx = pts[3 * cur + 0];
        float cy = pts[3 * cur + 1];
        float cz = pts[3 * cur + 2];
        if (t == 0) {
            g_centers[(b * K + k) * 3 + 0] = cx;
            g_centers[(b * K + k) * 3 + 1] = cy;
            g_centers[(b * K + k) * 3 + 2] = cz;
        }
        u64 nc2x = pack2(-cx, -cx);
        u64 nc2y = pack2(-cy, -cy);
        u64 nc2z = pack2(-cz, -cz);
#pragma unroll
        for (int j = 0; j < 4; j++) {
            u64 dx = add2(px2[j], nc2x);
            u64 dy = add2(py2[j], nc2y);
            u64 dz = add2(pz2[j], nc2z);
            u64 d  = mul2(dx, dx);
            d = fma2(dy, dy, d);
            d = fma2(dz, dz, d);
            float2 f = unpack2(d);
            md[2 * j]     = fminf(md[2 * j],     f.x);
            md[2 * j + 1] = fminf(md[2 * j + 1], f.y);
        }
        float tv = fmaxf(fmaxf(fmaxf(md[0], md[1]), fmaxf(md[2], md[3])),
                         fmaxf(fmaxf(md[4], md[5]), fmaxf(md[6], md[7])));
        // nonneg float bits are order-preserving as uint
        unsigned tb = __float_as_uint(tv);
        unsigned wv = __reduce_max_sync(0xffffffffu, tb);
        unsigned li = 0xffffffffu;
        if (tb == wv) {
#pragma unroll
            for (int s = 0; s < 8; s++)
                if (__float_as_uint(md[s]) == wv)
                    li = min(li, (unsigned)(t + s * 1024));
        }
        li = __reduce_min_sync(0xffffffffu, li);
        if (lane == 0) { s_v[k & 1][w] = wv; s_i[k & 1][w] = li; }
        __syncthreads();
        // every warp redundantly reduces the 32 per-warp (val, idx) pairs:
        // identical inputs -> identical cur; no second barrier needed.
        unsigned v  = s_v[k & 1][lane];
        unsigned ix = s_i[k & 1][lane];
        unsigned m  = __reduce_max_sync(0xffffffffu, v);
        unsigned cand = (v == m) ? ix : 0xffffffffu;
        cur = (int)__reduce_min_sync(0xffffffffu, cand);
    }
}

// ---------------------------------------------------------------------------
// Exact key (explicit intrinsics, bit-identical everywhere it is called)
// ---------------------------------------------------------------------------
__device__ __forceinline__ unsigned f2key(float f) {
    unsigned bits = __float_as_uint(f);
    return (bits & 0x80000000u) ? ~bits : (bits | 0x80000000u);
}
__device__ __forceinline__ unsigned d2key(float px, float py, float pz,
                                          float cx, float cy, float cz, float cc) {
    float pp  = __fmaf_rn(pz, pz, __fmaf_rn(py, py, __fmul_rn(px, px)));
    float dot = __fmaf_rn(cz, pz, __fmaf_rn(cy, py, __fmul_rn(cx, px)));
    float d2  = __fmaf_rn(-2.0f, dot, __fadd_rn(cc, pp));
    return f2key(d2);
}

// ---------------------------------------------------------------------------
// KNN (R12 version, measured ~52us — UNCHANGED): RPC=2 rows/CTA, 512 thr,
// 16-bit prefixes, interpolated threshold, collect, exact recompute + sort.
// ---------------------------------------------------------------------------
extern "C" __global__ void __launch_bounds__(THR)
knn_kernel(const float* __restrict__ points, void* __restrict__ d_out,
           int is_f32) {
    extern __shared__ char sm[];
    u16* s_pre = (u16*)sm;                        // RPC*N*2 = 32KB
    u64* s_cp  = (u64*)(sm + RPC * N * 2);        // CAPF*8  =  4KB

    __shared__ unsigned s_wmin[THR / 32];
    __shared__ int      s_cnt;
    __shared__ u64      s_minw[THR / 32];
    __shared__ u64      s_last;

    const int row0 = blockIdx.x * RPC;   // 2 consecutive rows, same batch
    const int b    = row0 >> 7;
    const int t    = threadIdx.x;
    const int lane = t & 31, w = t >> 5;
    const int NW   = THR / 32;
    const unsigned lmask_lt = (1u << lane) - 1u;
    const float* gp = points + (size_t)b * N * 3;

    float cx[RPC], cy[RPC], cz[RPC], cc[RPC];
#pragma unroll
    for (int r = 0; r < RPC; r++) {
        const float* c = &g_centers[(row0 + r) * 3];
        cx[r] = c[0]; cy[r] = c[1]; cz[r] = c[2];
        cc[r] = __fmaf_rn(cz[r], cz[r],
                __fmaf_rn(cy[r], cy[r], __fmul_rn(cx[r], cx[r])));
    }

    // Pass 1: one point read serves both rows; per-thread min prefix per row
    unsigned tmin0 = 0xffffu, tmin1 = 0xffffu;
#pragma unroll 4
    for (int j = 0; j < N / THR; j++) {
        int n = t + j * THR;
        float px = gp[3 * n + 0], py = gp[3 * n + 1], pz = gp[3 * n + 2];
        unsigned p0 = d2key(px, py, pz, cx[0], cy[0], cz[0], cc[0]) >> 16;
        unsigned p1 = d2key(px, py, pz, cx[1], cy[1], cz[1], cc[1]) >> 16;
        s_pre[n]     = (u16)p0;
        s_pre[N + n] = (u16)p1;
        tmin0 = min(tmin0, p0);
        tmin1 = min(tmin1, p1);
    }

    for (int r = 0; r < RPC; r++) {
        const u16* pre_row = &s_pre[r * N];
        const int  row = row0 + r;
        unsigned tmin = (r == 0) ? tmin0 : tmin1;

        tmin = __reduce_min_sync(0xffffffffu, tmin);
        if (lane == 0) s_wmin[w] = tmin;
        __syncthreads();

        // Initial probe: max of warp-min prefixes
        unsigned probe = 0u;
#pragma unroll
        for (int i = 0; i < NW; i++) probe = max(probe, s_wmin[i]);

        // Find T with cnt(T) in [PS, CAPC]
        unsigned klo = 0u, khi = 0xffffu;
        int chi = N;
        unsigned T = 0u;
        bool have = false;
        for (int iter = 0; iter < 18; iter++) {
            if (t == 0) s_cnt = 0;
            __syncthreads();
            int c = 0;
#pragma unroll 8
            for (int j = 0; j < N / THR; j++)
                c += (pre_row[t + j * THR] <= (u16)probe);
            c = __reduce_add_sync(0xffffffffu, c);
            if (lane == 0) atomicAdd(&s_cnt, c);
            __syncthreads();
            int cnt = s_cnt;
            __syncthreads();                   // protect next reset
            if (cnt >= PS && cnt <= CAPC) { T = probe; have = true; break; }
            if (cnt < PS) klo = probe; else { khi = probe; chi = cnt; }
            if (khi - klo <= 1u) break;

            unsigned next = klo + ((khi - klo) >> 1);
            if ((iter % 3) != 2 && probe >= 0x8000u && cnt > 0) {
                float d = __uint_as_float((probe << 16) & 0x7fffffffu);
                float cand = d * __powf(64.0f / (float)cnt, 0.6666667f);
                if (cand > 0.0f) {
                    unsigned ck = (__float_as_uint(cand) | 0x80000000u) >> 16;
                    if (ck > klo && ck < khi) next = ck;
                }
            }
            probe = next;
        }
        if (!have && chi <= CAPF) { T = khi; have = true; }

        if (have) {
            // --- collect survivors by prefix (warp-aggregated) ---
            if (t == 0) s_cnt = 0;
            __syncthreads();
#pragma unroll 8
            for (int j = 0; j < N / THR; j++) {
                int n = t + j * THR;
                bool p = (pre_row[n] <= (u16)T);
                unsigned m = __ballot_sync(0xffffffffu, p);
                if (m) {
                    int leader = __ffs(m) - 1;
                    int base = 0;
                    if (lane == leader) base = atomicAdd(&s_cnt, __popc(m));
                    base = __shfl_sync(0xffffffffu, base, leader);
                    if (p) {
                        int pos = base + __popc(m & lmask_lt);
                        if (pos < CAPF) s_cp[pos] = (u64)(unsigned)n;
                    }
                }
            }
            __syncthreads();
            const int C = min(s_cnt, CAPF);
            // --- recompute exact keys, pack (key<<32 | n) ---
            for (int i = t; i < C; i += THR) {
                int n = (int)(unsigned)s_cp[i];
                float px = gp[3 * n + 0], py = gp[3 * n + 1], pz = gp[3 * n + 2];
                unsigned key = d2key(px, py, pz, cx[r], cy[r], cz[r], cc[r]);
                s_cp[i] = ((u64)key << 32) | (unsigned)n;
            }
            __syncthreads();
            // --- exact stable rank sort (lexicographic (key,idx)) ---
            for (int jj = t; jj < C; jj += THR) {
                u64 me = s_cp[jj];
                int rk = 0;
                for (int m = 0; m < C; m++) rk += (s_cp[m] < me);
                if (rk < PS) {
                    int nj = (int)(unsigned)(me & 0xffffffffu);
                    if (is_f32) ((float*)d_out)[row * PS + rk] = (float)nj;
                    else        ((int*)d_out)[row * PS + rk] = nj;
                }
            }
        } else {
            // --- fallback (measure zero): 32 sequential mins, keys exact ---
            if (t == 0) s_last = 0ull;
            __syncthreads();
            for (int sel = 0; sel < PS; sel++) {
                u64 last = s_last;
                u64 best = 0xffffffffffffffffull;
                for (int j = 0; j < N / THR; j++) {
                    int n = t + j * THR;
                    float px = gp[3 * n + 0], py = gp[3 * n + 1], pz = gp[3 * n + 2];
                    unsigned key = d2key(px, py, pz, cx[r], cy[r], cz[r], cc[r]);
                    u64 v = ((u64)key << 32) | (unsigned)n;
                    if (v > last && v < best) best = v;
                }
#pragma unroll
                for (int off = 16; off; off >>= 1) {
                    u64 o = __shfl_down_sync(0xffffffffu, best, off);
                    best = o < best ? o : best;
                }
                if (lane == 0) s_minw[w] = best;
                __syncthreads();
                if (t == 0) {
                    u64 m = s_minw[0];
                    for (int i = 1; i < NW; i++) m = s_minw[i] < m ? s_minw[i] : m;
                    int nj = (int)(unsigned)(m & 0xffffffffu);
                    if (is_f32) ((float*)d_out)[row * PS + sel] = (float)nj;
                    else        ((int*)d_out)[row * PS + sel] = nj;
                    s_last = m;
                }
                __syncthreads();
            }
        }
        __syncthreads();
    }
}

// ---------------------------------------------------------------------------
// Centers epilogue (f32 layout only)
// ---------------------------------------------------------------------------
extern "C" __global__ void epilogue_centers(float* __restrict__ out, int out_size) {
    int i = blockIdx.x * 256 + threadIdx.x;
    int dst = B * K * PS + i;
    if (i < B * K * 3 && dst < out_size) out[dst] = g_centers[i];
}

// ---------------------------------------------------------------------------
extern "C" void kernel_launch(void* const* d_in, const int* in_sizes, int n_in,
                              void* d_out, int out_size) {
    (void)in_sizes; (void)n_in;
    const float* points = (const float*)d_in[0];

    const int fps_smem = N * 3 * (int)sizeof(float);
    const int knn_smem = RPC * N * 2 + CAPF * 8;

    cudaFuncSetAttribute(fps_kernel,
                         cudaFuncAttributeMaxDynamicSharedMemorySize, fps_smem);
    cudaFuncSetAttribute(knn_kernel,
                         cudaFuncAttributeMaxDynamicSharedMemorySize, knn_smem);

    const int is_f32 = (out_size != B * K * PS);

    fps_kernel<<<B, 1024, fps_smem>>>(points);
    knn_kernel<<<B * K / RPC, THR, knn_smem>>>(points, d_out, is_f32);

    if (is_f32) {
        int nc = B * K * 3;
        epilogue_centers<<<(nc + 255) / 256, 256>>>((float*)d_out, out_size);
    }
}

// round 16
// speedup vs baseline: 1.3829x; 1.0532x over previous
#include <cuda_runtime.h>
#include <math_constants.h>
#include <stdint.h>

#define B  32
#define N  8192
#define K  128
#define PS 32

#define CAPC 128        // accept window upper bound (sort stays tiny)
#define CAPF 512        // stuck-bracket collect cap
#define RPC  2          // rows per CTA (shared point reads)
#define THR  512        // KNN threads per CTA
#define THRF 512        // FPS threads per CTA (16 pts/thread)

typedef unsigned long long u64;
typedef unsigned short u16;

// Scratch (allocation-free rule: __device__ globals)
__device__ float g_centers[B * K * 3];

// ---------------------------------------------------------------------------
// f32x2 packed helpers (one fma-pipe instr = 2 IEEE .rn ops, bit-identical)
// ---------------------------------------------------------------------------
__device__ __forceinline__ u64 pack2(float lo, float hi) {
    u64 r; asm("mov.b64 %0, {%1, %2};" : "=l"(r) : "f"(lo), "f"(hi)); return r;
}
__device__ __forceinline__ float2 unpack2(u64 v) {
    float2 f; asm("mov.b64 {%0, %1}, %2;" : "=f"(f.x), "=f"(f.y) : "l"(v)); return f;
}
__device__ __forceinline__ u64 add2(u64 a, u64 b) {
    u64 d; asm("add.rn.f32x2 %0, %1, %2;" : "=l"(d) : "l"(a), "l"(b)); return d;
}
__device__ __forceinline__ u64 mul2(u64 a, u64 b) {
    u64 d; asm("mul.rn.f32x2 %0, %1, %2;" : "=l"(d) : "l"(a), "l"(b)); return d;
}
__device__ __forceinline__ u64 fma2(u64 a, u64 b, u64 c) {
    u64 d; asm("fma.rn.f32x2 %0, %1, %2, %3;" : "=l"(d) : "l"(a), "l"(b), "l"(c)); return d;
}

// ---------------------------------------------------------------------------
// FPS: one block/batch, 512 threads x 16 pts/thread (same fma-pipe work as
// 1024x8, but HALF the warps -> half the same-address atomic chain + barrier
// spread). Reduction = measured-best R7 scheme: value REDUX + smem atomicMax,
// guarded equality scan + atomicMin (exact jnp.argmax first-occurrence).
// ---------------------------------------------------------------------------
extern "C" __global__ void __launch_bounds__(THRF, 1)
fps_kernel(const float* __restrict__ points) {
    extern __shared__ float pts[];      // [N*3] = 96KB
    __shared__ unsigned s_maxb[K];
    __shared__ int      s_idx[K];

    const int b = blockIdx.x;
    const int t = threadIdx.x;
    const float* gp = points + (size_t)b * N * 3;

    for (int i = t; i < N * 3; i += THRF) pts[i] = gp[i];
    if (t < K) { s_maxb[t] = 0u; s_idx[t] = 0x7fffffff; }
    __syncthreads();

    // 16 points/thread as 8 packed pairs: slot s holds point t + s*THRF
    u64 px2[8], py2[8], pz2[8];
    float md[16];
#pragma unroll
    for (int j = 0; j < 8; j++) {
        int nlo = t + (2 * j) * THRF;
        int nhi = t + (2 * j + 1) * THRF;
        px2[j] = pack2(pts[3 * nlo + 0], pts[3 * nhi + 0]);
        py2[j] = pack2(pts[3 * nlo + 1], pts[3 * nhi + 1]);
        pz2[j] = pack2(pts[3 * nlo + 2], pts[3 * nhi + 2]);
        md[2 * j] = CUDART_INF_F; md[2 * j + 1] = CUDART_INF_F;
    }

    int cur = 0;
    const int lane = t & 31;
    for (int k = 0; k < K; k++) {
        float cx = pts[3 * cur + 0];
        float cy = pts[3 * cur + 1];
        float cz = pts[3 * cur + 2];
        if (t == 0) {
            g_centers[(b * K + k) * 3 + 0] = cx;
            g_centers[(b * K + k) * 3 + 1] = cy;
            g_centers[(b * K + k) * 3 + 2] = cz;
        }
        u64 nc2x = pack2(-cx, -cx);
        u64 nc2y = pack2(-cy, -cy);
        u64 nc2z = pack2(-cz, -cz);
#pragma unroll
        for (int j = 0; j < 8; j++) {
            u64 dx = add2(px2[j], nc2x);
            u64 dy = add2(py2[j], nc2y);
            u64 dz = add2(pz2[j], nc2z);
            u64 d  = mul2(dx, dx);
            d = fma2(dy, dy, d);
            d = fma2(dz, dz, d);
            float2 f = unpack2(d);          // register-pair alias: free
            md[2 * j]     = fminf(md[2 * j],     f.x);
            md[2 * j + 1] = fminf(md[2 * j + 1], f.y);
        }
        float m0 = fmaxf(fmaxf(fmaxf(md[0], md[1]),  fmaxf(md[2], md[3])),
                         fmaxf(fmaxf(md[4], md[5]),  fmaxf(md[6], md[7])));
        float m1 = fmaxf(fmaxf(fmaxf(md[8], md[9]),  fmaxf(md[10], md[11])),
                         fmaxf(fmaxf(md[12], md[13]), fmaxf(md[14], md[15])));
        float tv = fmaxf(m0, m1);
        // nonneg float bits are order-preserving as uint
        unsigned wv = __reduce_max_sync(0xffffffffu, __float_as_uint(tv));
        if (lane == 0) atomicMax(&s_maxb[k], wv);
        __syncthreads();
        const unsigned mb = s_maxb[k];
        if (wv == mb) {                 // warp-uniform guard
            int li = 0x7fffffff;
#pragma unroll
            for (int s = 0; s < 16; s++) {
                if (__float_as_uint(md[s]) == mb) li = min(li, t + s * THRF);
            }
            if (li != 0x7fffffff) atomicMin(&s_idx[k], li);
        }
        __syncthreads();
        cur = s_idx[k];
    }
}

// ---------------------------------------------------------------------------
// Exact key (explicit intrinsics, bit-identical everywhere it is called)
// ---------------------------------------------------------------------------
__device__ __forceinline__ unsigned f2key(float f) {
    unsigned bits = __float_as_uint(f);
    return (bits & 0x80000000u) ? ~bits : (bits | 0x80000000u);
}
__device__ __forceinline__ unsigned d2key(float px, float py, float pz,
                                          float cx, float cy, float cz, float cc) {
    float pp  = __fmaf_rn(pz, pz, __fmaf_rn(py, py, __fmul_rn(px, px)));
    float dot = __fmaf_rn(cz, pz, __fmaf_rn(cy, py, __fmul_rn(cx, px)));
    float d2  = __fmaf_rn(-2.0f, dot, __fadd_rn(cc, pp));
    return f2key(d2);
}

// ---------------------------------------------------------------------------
// KNN (R12 version, measured ~52us — UNCHANGED): RPC=2 rows/CTA, 512 thr,
// 16-bit prefixes, interpolated threshold, collect, exact recompute + sort.
// ---------------------------------------------------------------------------
extern "C" __global__ void __launch_bounds__(THR)
knn_kernel(const float* __restrict__ points, void* __restrict__ d_out,
           int is_f32) {
    extern __shared__ char sm[];
    u16* s_pre = (u16*)sm;                        // RPC*N*2 = 32KB
    u64* s_cp  = (u64*)(sm + RPC * N * 2);        // CAPF*8  =  4KB

    __shared__ unsigned s_wmin[THR / 32];
    __shared__ int      s_cnt;
    __shared__ u64      s_minw[THR / 32];
    __shared__ u64      s_last;

    const int row0 = blockIdx.x * RPC;   // 2 consecutive rows, same batch
    const int b    = row0 >> 7;
    const int t    = threadIdx.x;
    const int lane = t & 31, w = t >> 5;
    const int NW   = THR / 32;
    const unsigned lmask_lt = (1u << lane) - 1u;
    const float* gp = points + (size_t)b * N * 3;

    float cx[RPC], cy[RPC], cz[RPC], cc[RPC];
#pragma unroll
    for (int r = 0; r < RPC; r++) {
        const float* c = &g_centers[(row0 + r) * 3];
        cx[r] = c[0]; cy[r] = c[1]; cz[r] = c[2];
        cc[r] = __fmaf_rn(cz[r], cz[r],
                __fmaf_rn(cy[r], cy[r], __fmul_rn(cx[r], cx[r])));
    }

    // Pass 1: one point read serves both rows; per-thread min prefix per row
    unsigned tmin0 = 0xffffu, tmin1 = 0xffffu;
#pragma unroll 4
    for (int j = 0; j < N / THR; j++) {
        int n = t + j * THR;
        float px = gp[3 * n + 0], py = gp[3 * n + 1], pz = gp[3 * n + 2];
        unsigned p0 = d2key(px, py, pz, cx[0], cy[0], cz[0], cc[0]) >> 16;
        unsigned p1 = d2key(px, py, pz, cx[1], cy[1], cz[1], cc[1]) >> 16;
        s_pre[n]     = (u16)p0;
        s_pre[N + n] = (u16)p1;
        tmin0 = min(tmin0, p0);
        tmin1 = min(tmin1, p1);
    }

    for (int r = 0; r < RPC; r++) {
        const u16* pre_row = &s_pre[r * N];
        const int  row = row0 + r;
        unsigned tmin = (r == 0) ? tmin0 : tmin1;

        tmin = __reduce_min_sync(0xffffffffu, tmin);
        if (lane == 0) s_wmin[w] = tmin;
        __syncthreads();

        // Initial probe: max of warp-min prefixes
        unsigned probe = 0u;
#pragma unroll
        for (int i = 0; i < NW; i++) probe = max(probe, s_wmin[i]);

        // Find T with cnt(T) in [PS, CAPC]
        unsigned klo = 0u, khi = 0xffffu;
        int chi = N;
        unsigned T = 0u;
        bool have = false;
        for (int iter = 0; iter < 18; iter++) {
            if (t == 0) s_cnt = 0;
            __syncthreads();
            int c = 0;
#pragma unroll 8
            for (int j = 0; j < N / THR; j++)
                c += (pre_row[t + j * THR] <= (u16)probe);
            c = __reduce_add_sync(0xffffffffu, c);
            if (lane == 0) atomicAdd(&s_cnt, c);
            __syncthreads();
            int cnt = s_cnt;
            __syncthreads();                   // protect next reset
            if (cnt >= PS && cnt <= CAPC) { T = probe; have = true; break; }
            if (cnt < PS) klo = probe; else { khi = probe; chi = cnt; }
            if (khi - klo <= 1u) break;

            unsigned next = klo + ((khi - klo) >> 1);
            if ((iter % 3) != 2 && probe >= 0x8000u && cnt > 0) {
                float d = __uint_as_float((probe << 16) & 0x7fffffffu);
                float cand = d * __powf(64.0f / (float)cnt, 0.6666667f);
                if (cand > 0.0f) {
                    unsigned ck = (__float_as_uint(cand) | 0x80000000u) >> 16;
                    if (ck > klo && ck < khi) next = ck;
                }
            }
            probe = next;
        }
        if (!have && chi <= CAPF) { T = khi; have = true; }

        if (have) {
            // --- collect survivors by prefix (warp-aggregated) ---
            if (t == 0) s_cnt = 0;
            __syncthreads();
#pragma unroll 8
            for (int j = 0; j < N / THR; j++) {
                int n = t + j * THR;
                bool p = (pre_row[n] <= (u16)T);
                unsigned m = __ballot_sync(0xffffffffu, p);
                if (m) {
                    int leader = __ffs(m) - 1;
                    int base = 0;
                    if (lane == leader) base = atomicAdd(&s_cnt, __popc(m));
                    base = __shfl_sync(0xffffffffu, base, leader);
                    if (p) {
                        int pos = base + __popc(m & lmask_lt);
                        if (pos < CAPF) s_cp[pos] = (u64)(unsigned)n;
                    }
                }
            }
            __syncthreads();
            const int C = min(s_cnt, CAPF);
            // --- recompute exact keys, pack (key<<32 | n) ---
            for (int i = t; i < C; i += THR) {
                int n = (int)(unsigned)s_cp[i];
                float px = gp[3 * n + 0], py = gp[3 * n + 1], pz = gp[3 * n + 2];
                unsigned key = d2key(px, py, pz, cx[r], cy[r], cz[r], cc[r]);
                s_cp[i] = ((u64)key << 32) | (unsigned)n;
            }
            __syncthreads();
            // --- exact stable rank sort (lexicographic (key,idx)) ---
            for (int jj = t; jj < C; jj += THR) {
                u64 me = s_cp[jj];
                int rk = 0;
                for (int m = 0; m < C; m++) rk += (s_cp[m] < me);
                if (rk < PS) {
                    int nj = (int)(unsigned)(me & 0xffffffffu);
                    if (is_f32) ((float*)d_out)[row * PS + rk] = (float)nj;
                    else        ((int*)d_out)[row * PS + rk] = nj;
                }
            }
        } else {
            // --- fallback (measure zero): 32 sequential mins, keys exact ---
            if (t == 0) s_last = 0ull;
            __syncthreads();
            for (int sel = 0; sel < PS; sel++) {
                u64 last = s_last;
                u64 best = 0xffffffffffffffffull;
                for (int j = 0; j < N / THR; j++) {
                    int n = t + j * THR;
                    float px = gp[3 * n + 0], py = gp[3 * n + 1], pz = gp[3 * n + 2];
                    unsigned key = d2key(px, py, pz, cx[r], cy[r], cz[r], cc[r]);
                    u64 v = ((u64)key << 32) | (unsigned)n;
                    if (v > last && v < best) best = v;
                }
#pragma unroll
                for (int off = 16; off; off >>= 1) {
                    u64 o = __shfl_down_sync(0xffffffffu, best, off);
                    best = o < best ? o : best;
                }
                if (lane == 0) s_minw[w] = best;
                __syncthreads();
                if (t == 0) {
                    u64 m = s_minw[0];
                    for (int i = 1; i < NW; i++) m = s_minw[i] < m ? s_minw[i] : m;
                    int nj = (int)(unsigned)(m & 0xffffffffu);
                    if (is_f32) ((float*)d_out)[row * PS + sel] = (float)nj;
                    else        ((int*)d_out)[row * PS + sel] = nj;
                    s_last = m;
                }
                __syncthreads();
            }
        }
        __syncthreads();
    }
}

// ---------------------------------------------------------------------------
// Centers epilogue (f32 layout only)
// ---------------------------------------------------------------------------
extern "C" __global__ void epilogue_centers(float* __restrict__ out, int out_size) {
    int i = blockIdx.x * 256 + threadIdx.x;
    int dst = B * K * PS + i;
    if (i < B * K * 3 && dst < out_size) out[dst] = g_centers[i];
}

// ---------------------------------------------------------------------------
extern "C" void kernel_launch(void* const* d_in, const int* in_sizes, int n_in,
                              void* d_out, int out_size) {
    (void)in_sizes; (void)n_in;
    const float* points = (const float*)d_in[0];

    const int fps_smem = N * 3 * (int)sizeof(float);
    const int knn_smem = RPC * N * 2 + CAPF * 8;

    cudaFuncSetAttribute(fps_kernel,
                         cudaFuncAttributeMaxDynamicSharedMemorySize, fps_smem);
    cudaFuncSetAttribute(knn_kernel,
                         cudaFuncAttributeMaxDynamicSharedMemorySize, knn_smem);

    const int is_f32 = (out_size != B * K * PS);

    fps_kernel<<<B, THRF, fps_smem>>>(points);
    knn_kernel<<<B * K / RPC, THR, knn_smem>>>(points, d_out, is_f32);

    if (is_f32) {
        int nc = B * K * 3;
        epilogue_centers<<<(nc + 255) / 256, 256>>>((float*)d_out, out_size);
    }
}